// round 1
// baseline (speedup 1.0000x reference)
#include <cuda_runtime.h>

// DeepFilter: out[b,0,t,f<256] = sum_k spec_r[t+k-4,f]*c[k] - spec_i[t+k-4,f]*c[5+k]
//             out[b,1,t,f<256] = sum_k spec_i[t+k-4,f]*c[k] + spec_r[t+k-4,f]*c[5+k]
//             out[b,:,t,f>=256] = spec[b,:,t,f]
// spec:  (B=8, 2, T=4096, F=481) f32
// coefs: (B=8, 10, T=4096, 256) f32   (c[0..4]=real taps, c[5..9]=imag taps)

#define NUM_FREQS 256
#define FRAME_SIZE 5
#define T_DIM 4096
#define F_TOTAL 481
#define B_DIM 8

__global__ __launch_bounds__(512, 4)
void deepfilter_kernel(const float* __restrict__ spec,
                       const float* __restrict__ coefs,
                       float* __restrict__ out)
{
    const int f = threadIdx.x;
    if (f >= F_TOTAL) return;
    const int t = blockIdx.x;
    const int b = blockIdx.y;

    // strides
    const long spec_b  = (long)2 * T_DIM * F_TOTAL;
    const long spec_ch = (long)T_DIM * F_TOTAL;
    const long coef_b  = (long)2 * FRAME_SIZE * T_DIM * NUM_FREQS;
    const long coef_c  = (long)T_DIM * NUM_FREQS;

    const float* sp_r = spec + (long)b * spec_b + (long)t * F_TOTAL + f;
    const float* sp_i = sp_r + spec_ch;
    float* out_r = out + (long)b * spec_b + (long)t * F_TOTAL + f;
    float* out_i = out_r + spec_ch;

    if (f >= NUM_FREQS) {
        // passthrough
        *out_r = *sp_r;
        *out_i = *sp_i;
        return;
    }

    const float* cf = coefs + (long)b * coef_b + (long)t * NUM_FREQS + f;

    float acc_r = 0.0f;
    float acc_i = 0.0f;
    #pragma unroll
    for (int k = 0; k < FRAME_SIZE; k++) {
        const int ts = t + k - (FRAME_SIZE - 1);   // lookahead = 0
        const float cr = cf[(long)k * coef_c];
        const float ci = cf[(long)(FRAME_SIZE + k) * coef_c];
        if (ts >= 0) {
            const long off = (long)(ts - t) * F_TOTAL;
            const float sr = sp_r[off];
            const float si = sp_i[off];
            acc_r = fmaf(sr, cr, fmaf(-si, ci, acc_r));
            acc_i = fmaf(si, cr, fmaf(sr, ci, acc_i));
        }
    }
    *out_r = acc_r;
    *out_i = acc_i;
}

extern "C" void kernel_launch(void* const* d_in, const int* in_sizes, int n_in,
                              void* d_out, int out_size)
{
    const float* spec  = (const float*)d_in[0];
    const float* coefs = (const float*)d_in[1];
    float* out = (float*)d_out;

    dim3 grid(T_DIM, B_DIM);
    deepfilter_kernel<<<grid, 512>>>(spec, coefs, out);
}

// round 2
// speedup vs baseline: 1.0146x; 1.0146x over previous
#include <cuda_runtime.h>

// DeepFilter: out[b,0,t,f<256] = sum_k spec_r[t+k-4,f]*c[k] - spec_i[t+k-4,f]*c[5+k]
//             out[b,1,t,f<256] = sum_k spec_i[t+k-4,f]*c[k] + spec_r[t+k-4,f]*c[5+k]
//             out[b,:,t,f>=256] = spec[b,:,t,f]
// spec:  (B=8, 2, T=4096, F=481) f32
// coefs: (B=8, 10, T=4096, 256) f32   (c[0..4]=real taps, c[5..9]=imag taps)

#define NUM_FREQS 256
#define FRAME_SIZE 5
#define T_DIM 4096
#define F_TOTAL 481
#define B_DIM 8

__global__ __launch_bounds__(128, 8)
void deepfilter_kernel(const float* __restrict__ spec,
                       const float* __restrict__ coefs,
                       float* __restrict__ out)
{
    const int tid = threadIdx.x;
    const int t = blockIdx.x;
    const int b = blockIdx.y;

    const long spec_ch = (long)T_DIM * F_TOTAL;
    const long spec_b  = 2 * spec_ch;
    const long coef_c  = (long)T_DIM * NUM_FREQS;
    const long coef_b  = 2 * FRAME_SIZE * coef_c;

    const float* sp_base = spec + (long)b * spec_b + (long)t * F_TOTAL;
    float*       ot_base = out  + (long)b * spec_b + (long)t * F_TOTAL;

    if (tid < 64) {
        // Filtered region: 4 bins per thread, float4 coef loads (16B aligned:
        // coef row stride 256, channel/batch strides multiples of 4).
        const int f0 = tid * 4;
        const float* cf = coefs + (long)b * coef_b + (long)t * NUM_FREQS + f0;

        float ar0 = 0.f, ar1 = 0.f, ar2 = 0.f, ar3 = 0.f;
        float ai0 = 0.f, ai1 = 0.f, ai2 = 0.f, ai3 = 0.f;

        #pragma unroll
        for (int k = 0; k < FRAME_SIZE; k++) {
            const int ts = t + k - (FRAME_SIZE - 1);   // lookahead = 0
            if (ts >= 0) {
                const float4 cr = *(const float4*)(cf + (long)k * coef_c);
                const float4 ci = *(const float4*)(cf + (long)(FRAME_SIZE + k) * coef_c);

                const float* sr = sp_base + (long)(ts - t) * F_TOTAL + f0;
                const float* si = sr + spec_ch;

                const float sr0 = sr[0], sr1 = sr[1], sr2 = sr[2], sr3 = sr[3];
                const float si0 = si[0], si1 = si[1], si2 = si[2], si3 = si[3];

                ar0 = fmaf(sr0, cr.x, fmaf(-si0, ci.x, ar0));
                ar1 = fmaf(sr1, cr.y, fmaf(-si1, ci.y, ar1));
                ar2 = fmaf(sr2, cr.z, fmaf(-si2, ci.z, ar2));
                ar3 = fmaf(sr3, cr.w, fmaf(-si3, ci.w, ar3));

                ai0 = fmaf(si0, cr.x, fmaf(sr0, ci.x, ai0));
                ai1 = fmaf(si1, cr.y, fmaf(sr1, ci.y, ai1));
                ai2 = fmaf(si2, cr.z, fmaf(sr2, ci.z, ai2));
                ai3 = fmaf(si3, cr.w, fmaf(sr3, ci.w, ai3));
            }
        }

        float* outr = ot_base + f0;
        float* outi = outr + spec_ch;
        outr[0] = ar0; outr[1] = ar1; outr[2] = ar2; outr[3] = ar3;
        outi[0] = ai0; outi[1] = ai1; outi[2] = ai2; outi[3] = ai3;
    } else {
        // Passthrough region: bins 256..480, 4 bins per thread.
        const int f0 = NUM_FREQS + (tid - 64) * 4;
        #pragma unroll
        for (int j = 0; j < 4; j++) {
            const int f = f0 + j;
            if (f < F_TOTAL) {
                ot_base[f]           = sp_base[f];
                ot_base[spec_ch + f] = sp_base[spec_ch + f];
            }
        }
    }
}

extern "C" void kernel_launch(void* const* d_in, const int* in_sizes, int n_in,
                              void* d_out, int out_size)
{
    const float* spec  = (const float*)d_in[0];
    const float* coefs = (const float*)d_in[1];
    float* out = (float*)d_out;

    dim3 grid(T_DIM, B_DIM);
    deepfilter_kernel<<<grid, 128>>>(spec, coefs, out);
}